// round 12
// baseline (speedup 1.0000x reference)
#include <cuda_runtime.h>
#include <cuda_fp16.h>
#include <math.h>
#include <stdint.h>

#define HIDDEN 1024
#define INTER  2048
#define NEXP   8
#define NTOK   8192
#define SLOTS  (NTOK * 2)          // 16384
#define BM 128
#define BN 256
#define BK 32
#define SLOTS_PAD (SLOTS + BM)
#define MAX_TILES (SLOTS / BM + NEXP)  // 136

#define STRIDE 80                    // padded smem row bytes (32 fp16 = 64B + 16B pad)
#define A_TILEBYTES (128 * STRIDE)   // 10240
#define B_TILEBYTES (256 * STRIDE)   // 20480
#define STAGEBYTES (A_TILEBYTES + B_TILEBYTES)  // 30720
#define NSTAGE 3
#define SMEM_TOTAL (NSTAGE * STAGEBYTES)        // 92160

// ---------------- device scratch (static, no allocations) ----------------
__device__ int   g_cnt2[NEXP];
__device__ int   g_cnt1[NEXP];
__device__ float g_probsum[NEXP];
__device__ int   g_offset[NEXP + 1];
__device__ int   g_cursor[NEXP];
__device__ int   g_tile_e[MAX_TILES];
__device__ int   g_tile_row[MAX_TILES];
__device__ int   g_ntiles;
__device__ int   g_tok_list[SLOTS_PAD];
__device__ float g_slot_w[SLOTS_PAD];
__device__ float g_topw[SLOTS];
__device__ int   g_topi[SLOTS];

__device__ __half g_xh[NTOK * HIDDEN];
__device__ __half g_w1t[NEXP * INTER * HIDDEN];   // [E][N][K] K-major fp16
__device__ __half g_w2t[NEXP * HIDDEN * INTER];
__device__ __half g_hb[(size_t)SLOTS_PAD * INTER];

// ---------------- PTX helpers ----------------
__device__ __forceinline__ uint32_t smem_u32(const void* p) {
    uint32_t a;
    asm("{ .reg .u64 t; cvta.to.shared.u64 t, %1; cvt.u32.u64 %0, t; }" : "=r"(a) : "l"(p));
    return a;
}
#define CP_ASYNC16(dst, src) \
    asm volatile("cp.async.cg.shared.global [%0], [%1], 16;" :: "r"(dst), "l"(src) : "memory")
#define CP_COMMIT() asm volatile("cp.async.commit_group;" ::: "memory")
#define CP_WAIT(n)  asm volatile("cp.async.wait_group %0;" :: "n"(n) : "memory")

#define LDSM_X4(r, a) \
    asm volatile("ldmatrix.sync.aligned.m8n8.x4.shared.b16 {%0,%1,%2,%3}, [%4];" \
        : "=r"((r)[0]), "=r"((r)[1]), "=r"((r)[2]), "=r"((r)[3]) : "r"(a))

#define MMA16816(c, a, b0, b1) \
    asm volatile("mma.sync.aligned.m16n8k16.row.col.f32.f16.f16.f32 " \
        "{%0,%1,%2,%3}, {%4,%5,%6,%7}, {%8,%9}, {%0,%1,%2,%3};" \
        : "+f"((c)[0]), "+f"((c)[1]), "+f"((c)[2]), "+f"((c)[3]) \
        : "r"((a)[0]), "r"((a)[1]), "r"((a)[2]), "r"((a)[3]), "r"(b0), "r"(b1))

// ---------------- fused prep: counters, pad lists, zero out, convert x ----
__global__ void prep_kernel(const float* __restrict__ x, float* __restrict__ out) {
    int gid = blockIdx.x * blockDim.x + threadIdx.x;
    int gsz = gridDim.x * blockDim.x;
    if (gid < NEXP) { g_cnt1[gid] = 0; g_cnt2[gid] = 0; g_cursor[gid] = 0; g_probsum[gid] = 0.f; }
    for (int j = gid; j < SLOTS_PAD; j += gsz) { g_tok_list[j] = 0; g_slot_w[j] = 0.f; }
    float4 z; z.x = z.y = z.z = z.w = 0.f;
    for (int j = gid; j < NTOK * HIDDEN / 4; j += gsz) {
        ((float4*)out)[j] = z;
        float4 v = ((const float4*)x)[j];
        __half2 h0; h0.x = __float2half(v.x); h0.y = __float2half(v.y);
        __half2 h1; h1.x = __float2half(v.z); h1.y = __float2half(v.w);
        ((__half2*)g_xh)[2 * j]     = h0;
        ((__half2*)g_xh)[2 * j + 1] = h1;
    }
}

// ---------------- router: 1 warp per token ----------------
__global__ void router_kernel(const float* __restrict__ x, const float* __restrict__ wr) {
    int gwarp = (blockIdx.x * blockDim.x + threadIdx.x) >> 5;
    int lane = threadIdx.x & 31;
    if (gwarp >= NTOK) return;
    const float* xr = x + (size_t)gwarp * HIDDEN;
    float acc[NEXP];
#pragma unroll
    for (int e = 0; e < NEXP; e++) acc[e] = 0.f;
    for (int k = lane; k < HIDDEN; k += 32) {
        float xv = xr[k];
        const float* w = wr + (size_t)k * NEXP;
#pragma unroll
        for (int e = 0; e < NEXP; e++) acc[e] += xv * w[e];
    }
#pragma unroll
    for (int off = 16; off; off >>= 1)
#pragma unroll
        for (int e = 0; e < NEXP; e++) acc[e] += __shfl_xor_sync(0xffffffffu, acc[e], off);
    if (lane != 0) return;

    float mx = acc[0];
#pragma unroll
    for (int e = 1; e < NEXP; e++) mx = fmaxf(mx, acc[e]);
    float p[NEXP], s = 0.f;
#pragma unroll
    for (int e = 0; e < NEXP; e++) { p[e] = expf(acc[e] - mx); s += p[e]; }
    float inv = 1.f / s;
#pragma unroll
    for (int e = 0; e < NEXP; e++) p[e] *= inv;

    int i0 = 0; float v0 = p[0];
#pragma unroll
    for (int e = 1; e < NEXP; e++) if (p[e] > v0) { v0 = p[e]; i0 = e; }
    int i1 = -1; float v1 = -1.f;
#pragma unroll
    for (int e = 0; e < NEXP; e++) { if (e == i0) continue; if (p[e] > v1) { v1 = p[e]; i1 = e; } }
    float wsum = v0 + v1;
    g_topi[gwarp * 2 + 0] = i0; g_topw[gwarp * 2 + 0] = v0 / wsum;
    g_topi[gwarp * 2 + 1] = i1; g_topw[gwarp * 2 + 1] = v1 / wsum;
    atomicAdd(&g_cnt1[i0], 1);
    atomicAdd(&g_cnt2[i0], 1);
    atomicAdd(&g_cnt2[i1], 1);
#pragma unroll
    for (int e = 0; e < NEXP; e++) atomicAdd(&g_probsum[e], p[e]);
}

// ---------------- offsets + tile list + aux loss ----------------
__global__ void offsets_kernel(float* __restrict__ out, int out_size) {
    int t = threadIdx.x;
    if (t == 0) {
        int off = 0;
        for (int e = 0; e < NEXP; e++) { g_offset[e] = off; off += g_cnt2[e]; }
        g_offset[NEXP] = off;
        int idx = 0;
        for (int e = 0; e < NEXP; e++) {
            int nt = (g_cnt2[e] + BM - 1) / BM;
            int base = g_offset[e];
            for (int k = 0; k < nt; k++) { g_tile_e[idx] = e; g_tile_row[idx] = base + k * BM; idx++; }
        }
        g_ntiles = idx;
    } else if (t == 32 && out_size > NTOK * HIDDEN) {
        float aux = 0.f;
        for (int e = 0; e < NEXP; e++)
            aux += ((float)g_cnt1[e] / (float)NTOK) * (g_probsum[e] / (float)NTOK);
        out[out_size - 1] = aux * (float)NEXP;
    }
}

// ---------------- scatter ----------------
__global__ void scatter_kernel() {
    int i = blockIdx.x * blockDim.x + threadIdx.x;
    if (i >= SLOTS) return;
    int e = g_topi[i];
    int pos = atomicAdd(&g_cursor[e], 1);
    int slot = g_offset[e] + pos;
    g_tok_list[slot] = i >> 1;
    g_slot_w[slot] = g_topw[i];
}

// ---------------- W transpose + convert: [E][K][N] f32 -> [E][N][K] fp16 ----
__global__ void wconv_kernel(const float* __restrict__ W,
                             __half* __restrict__ out,
                             int K, int N) {
    __shared__ float t[32][33];
    int e = blockIdx.z;
    const float* Wb = W + (size_t)e * K * N;
    int n0 = blockIdx.x * 32, k0 = blockIdx.y * 32;
    for (int i = threadIdx.y; i < 32; i += 8)
        t[i][threadIdx.x] = Wb[(size_t)(k0 + i) * N + n0 + threadIdx.x];
    __syncthreads();
    for (int i = threadIdx.y; i < 32; i += 8) {
        float v = t[threadIdx.x][i];
        out[((size_t)e * N + n0 + i) * K + k0 + threadIdx.x] = __float2half(v);
    }
}

// ---------------- grouped fp16 mma.sync GEMM (BM=128, BN=256) ----------------
// mode 0 (GEMM1): gathered A = x, SiLU, fp16 out to hb
// mode 1 (GEMM2): A = hb, fused combine: atomicAdd(out[token], w*val)
__global__ __launch_bounds__(256)
void moe_gemm(const __half* __restrict__ A,
              const __half* __restrict__ Bw,
              int K, int Nd, int mode,
              __half* __restrict__ outH, float* __restrict__ outF) {
    int tile = blockIdx.x;
    if (tile >= g_ntiles) return;
    int e = g_tile_e[tile];
    int row0 = g_tile_row[tile];
    int mcount = g_offset[e + 1] - row0;
    if (mcount > BM) mcount = BM;
    int n0 = blockIdx.y * BN;

    extern __shared__ char smem[];
    uint32_t sb = smem_u32(smem);
    int tid = threadIdx.x;
    int lane = tid & 31;
    int wid = tid >> 5;
    int warp_m = wid & 1;        // 2 -> 64 rows each
    int warp_n = wid >> 1;       // 4 -> 64 cols each

    // ---- cp.async offsets: A 2 chunks/thread, B 4 chunks/thread (16B each) ----
    uint32_t a_src[2], a_dst[2], b_src[4], b_dst[4];
#pragma unroll
    for (int i = 0; i < 2; i++) {
        int id = tid + i * 256;
        int row = id >> 2, c16 = id & 3;
        int srow = (mode == 0) ? g_tok_list[row0 + row] : (row0 + row);
        a_src[i] = (uint32_t)srow * (uint32_t)K + c16 * 8;
        a_dst[i] = row * STRIDE + c16 * 16;
    }
#pragma unroll
    for (int i = 0; i < 4; i++) {
        int id = tid + i * 256;
        int row = id >> 2, c16 = id & 3;
        b_src[i] = ((uint32_t)e * (uint32_t)Nd + n0 + row) * (uint32_t)K + c16 * 8;
        b_dst[i] = row * STRIDE + c16 * 16;
    }

    float acc[4][8][4];
#pragma unroll
    for (int m = 0; m < 4; m++)
#pragma unroll
        for (int n = 0; n < 8; n++)
#pragma unroll
            for (int r = 0; r < 4; r++) acc[m][n][r] = 0.f;

    // ldmatrix smem-relative offsets
    uint32_t a_rel[4], b_rel[4];
    {
        int row_a = warp_m * 64 + (lane & 15);
        int ka = (lane & 16) ? 16 : 0;
#pragma unroll
        for (int m = 0; m < 4; m++) a_rel[m] = (row_a + m * 16) * STRIDE + ka;
        int row_b = warp_n * 64 + (lane & 7) + ((lane & 16) >> 1);
        int kb = (lane & 8) * 2;
#pragma unroll
        for (int p = 0; p < 4; p++) b_rel[p] = (row_b + p * 16) * STRIDE + kb;
    }

    int nch = K / BK;

    // prologue: stages 0 and 1
#pragma unroll
    for (int ps = 0; ps < 2; ps++) {
        uint32_t base = sb + ps * STAGEBYTES;
        uint32_t k0 = ps * BK;
#pragma unroll
        for (int i = 0; i < 2; i++)
            CP_ASYNC16(base + a_dst[i], (const char*)(A + a_src[i] + k0));
#pragma unroll
        for (int i = 0; i < 4; i++)
            CP_ASYNC16(base + A_TILEBYTES + b_dst[i], (const char*)(Bw + b_src[i] + k0));
        CP_COMMIT();
    }

    int slot = 0;
    for (int ch = 0; ch < nch; ch++) {
        if (ch + 1 < nch) CP_WAIT(1); else CP_WAIT(0);
        __syncthreads();

        if (ch + 2 < nch) {
            int ns = slot + 2; if (ns >= NSTAGE) ns -= NSTAGE;
            uint32_t base = sb + ns * STAGEBYTES;
            uint32_t k0 = (ch + 2) * BK;
#pragma unroll
            for (int i = 0; i < 2; i++)
                CP_ASYNC16(base + a_dst[i], (const char*)(A + a_src[i] + k0));
#pragma unroll
            for (int i = 0; i < 4; i++)
                CP_ASYNC16(base + A_TILEBYTES + b_dst[i], (const char*)(Bw + b_src[i] + k0));
            CP_COMMIT();
        }

        uint32_t Ab = sb + slot * STAGEBYTES;
        uint32_t Bb = Ab + A_TILEBYTES;

#pragma unroll
        for (int ks = 0; ks < 2; ks++) {
            uint32_t kb = ks * 32;  // 16 fp16 = 32 bytes
            uint32_t Ar[4][4], Br[4][4];
#pragma unroll
            for (int m = 0; m < 4; m++)
                LDSM_X4(Ar[m], Ab + a_rel[m] + kb);
#pragma unroll
            for (int p = 0; p < 4; p++)
                LDSM_X4(Br[p], Bb + b_rel[p] + kb);
#pragma unroll
            for (int n = 0; n < 8; n++) {
                int p = n >> 1, q = (n & 1) * 2;
                uint32_t b0 = Br[p][q], b1 = Br[p][q + 1];
#pragma unroll
                for (int m = 0; m < 4; m++)
                    MMA16816(acc[m][n], Ar[m], b0, b1);
            }
        }
        slot++; if (slot >= NSTAGE) slot = 0;
    }

    // ---- epilogue ----
    int g = lane >> 2, tig = lane & 3;
    if (mode == 0) {
#pragma unroll
        for (int m = 0; m < 4; m++) {
            int lr = warp_m * 64 + m * 16 + g;
#pragma unroll
            for (int h = 0; h < 2; h++) {
                int lrow = lr + h * 8;
                if (lrow >= mcount) continue;
                size_t grow = (size_t)(row0 + lrow);
#pragma unroll
                for (int n = 0; n < 8; n++) {
                    int col = n0 + warp_n * 64 + n * 8 + 2 * tig;
                    float f0 = acc[m][n][h * 2 + 0];
                    float f1 = acc[m][n][h * 2 + 1];
                    f0 = f0 / (1.f + expf(-f0));
                    f1 = f1 / (1.f + expf(-f1));
                    __half2 hv; hv.x = __float2half(f0); hv.y = __float2half(f1);
                    *reinterpret_cast<__half2*>(outH + grow * Nd + col) = hv;
                }
            }
        }
    } else {
#pragma unroll
        for (int m = 0; m < 4; m++) {
            int lr = warp_m * 64 + m * 16 + g;
#pragma unroll
            for (int h = 0; h < 2; h++) {
                int lrow = lr + h * 8;
                if (lrow >= mcount) continue;
                int srow = row0 + lrow;
                int token = g_tok_list[srow];
                float w = g_slot_w[srow];
                float* obase = outF + (size_t)token * HIDDEN;
#pragma unroll
                for (int n = 0; n < 8; n++) {
                    int col = n0 + warp_n * 64 + n * 8 + 2 * tig;
                    atomicAdd(obase + col,     w * acc[m][n][h * 2 + 0]);
                    atomicAdd(obase + col + 1, w * acc[m][n][h * 2 + 1]);
                }
            }
        }
    }
}

// ---------------- launch ----------------
extern "C" void kernel_launch(void* const* d_in, const int* in_sizes, int n_in,
                              void* d_out, int out_size) {
    const float* x  = (const float*)d_in[0];
    const float* wr = (const float*)d_in[1];
    const float* w1 = (const float*)d_in[2];
    const float* w2 = (const float*)d_in[3];
    float* out = (float*)d_out;

    static int configured = 0;
    if (!configured) {
        cudaFuncSetAttribute(moe_gemm, cudaFuncAttributeMaxDynamicSharedMemorySize, SMEM_TOTAL);
        configured = 1;
    }

    __half *xh, *w1t, *w2t, *hb;
    cudaGetSymbolAddress((void**)&xh,  g_xh);
    cudaGetSymbolAddress((void**)&w1t, g_w1t);
    cudaGetSymbolAddress((void**)&w2t, g_w2t);
    cudaGetSymbolAddress((void**)&hb,  g_hb);

    prep_kernel<<<512, 256>>>(x, out);
    router_kernel<<<(NTOK * 32 + 255) / 256, 256>>>(x, wr);
    offsets_kernel<<<1, 64>>>(out, out_size);
    scatter_kernel<<<(SLOTS + 255) / 256, 256>>>();

    wconv_kernel<<<dim3(INTER / 32, HIDDEN / 32, NEXP), dim3(32, 8)>>>(w1, w1t, HIDDEN, INTER);
    wconv_kernel<<<dim3(HIDDEN / 32, INTER / 32, NEXP), dim3(32, 8)>>>(w2, w2t, INTER, HIDDEN);

    // GEMM1: hb[slot, INTER] = silu(gather(x) @ W1), fp16
    moe_gemm<<<dim3(MAX_TILES, INTER / BN), 256, SMEM_TOTAL>>>(
        xh, w1t, HIDDEN, INTER, 0, hb, (float*)0);
    // GEMM2 + fused combine: out[token] += w * (hb @ W2)
    moe_gemm<<<dim3(MAX_TILES, HIDDEN / BN), 256, SMEM_TOTAL>>>(
        hb, w2t, INTER, HIDDEN, 1, (__half*)0, out);
}

// round 13
// speedup vs baseline: 1.2391x; 1.2391x over previous
#include <cuda_runtime.h>
#include <cuda_fp16.h>
#include <math.h>
#include <stdint.h>

#define HIDDEN 1024
#define INTER  2048
#define NEXP   8
#define NTOK   8192
#define SLOTS  (NTOK * 2)          // 16384
#define BM 128
#define BN 128
#define BK 64
#define SLOTS_PAD (SLOTS + BM)
#define MAX_TILES (SLOTS / BM + NEXP)  // 136

#define STRIDE 144                   // 64 fp16 = 128B data + 16B pad
#define A_TILEBYTES (128 * STRIDE)   // 18432
#define B_TILEBYTES (128 * STRIDE)   // 18432
#define STAGEBYTES (A_TILEBYTES + B_TILEBYTES)  // 36864
#define NSTAGE 3
#define SMEM_TOTAL (NSTAGE * STAGEBYTES)        // 110592 per CTA, 2 CTAs = 216KB

// ---------------- device scratch (static, no allocations) ----------------
__device__ int   g_cnt2[NEXP];
__device__ int   g_cnt1[NEXP];
__device__ float g_probsum[NEXP];
__device__ int   g_offset[NEXP + 1];
__device__ int   g_cursor[NEXP];
__device__ int   g_tile_e[MAX_TILES];
__device__ int   g_tile_row[MAX_TILES];
__device__ int   g_ntiles;
__device__ int   g_tok_list[SLOTS_PAD];
__device__ float g_slot_w[SLOTS_PAD];
__device__ float g_topw[SLOTS];
__device__ int   g_topi[SLOTS];

__device__ __half g_xh[NTOK * HIDDEN];
__device__ __half g_w1t[NEXP * INTER * HIDDEN];   // [E][N][K] K-major fp16
__device__ __half g_w2t[NEXP * HIDDEN * INTER];
__device__ __half g_hb[(size_t)SLOTS_PAD * INTER];

// ---------------- PTX helpers ----------------
__device__ __forceinline__ uint32_t smem_u32(const void* p) {
    uint32_t a;
    asm("{ .reg .u64 t; cvta.to.shared.u64 t, %1; cvt.u32.u64 %0, t; }" : "=r"(a) : "l"(p));
    return a;
}
#define CP_ASYNC16(dst, src) \
    asm volatile("cp.async.cg.shared.global [%0], [%1], 16;" :: "r"(dst), "l"(src) : "memory")
#define CP_COMMIT() asm volatile("cp.async.commit_group;" ::: "memory")
#define CP_WAIT(n)  asm volatile("cp.async.wait_group %0;" :: "n"(n) : "memory")

#define LDSM_X4(r, a) \
    asm volatile("ldmatrix.sync.aligned.m8n8.x4.shared.b16 {%0,%1,%2,%3}, [%4];" \
        : "=r"((r)[0]), "=r"((r)[1]), "=r"((r)[2]), "=r"((r)[3]) : "r"(a))

#define MMA16816(c, a, b0, b1) \
    asm volatile("mma.sync.aligned.m16n8k16.row.col.f32.f16.f16.f32 " \
        "{%0,%1,%2,%3}, {%4,%5,%6,%7}, {%8,%9}, {%0,%1,%2,%3};" \
        : "+f"((c)[0]), "+f"((c)[1]), "+f"((c)[2]), "+f"((c)[3]) \
        : "r"((a)[0]), "r"((a)[1]), "r"((a)[2]), "r"((a)[3]), "r"(b0), "r"(b1))

// ---------------- fused prep: counters, pad lists, zero out, convert x ----
__global__ void prep_kernel(const float* __restrict__ x, float* __restrict__ out) {
    int gid = blockIdx.x * blockDim.x + threadIdx.x;
    int gsz = gridDim.x * blockDim.x;
    if (gid < NEXP) { g_cnt1[gid] = 0; g_cnt2[gid] = 0; g_cursor[gid] = 0; g_probsum[gid] = 0.f; }
    for (int j = gid; j < SLOTS_PAD; j += gsz) { g_tok_list[j] = 0; g_slot_w[j] = 0.f; }
    float4 z; z.x = z.y = z.z = z.w = 0.f;
    for (int j = gid; j < NTOK * HIDDEN / 4; j += gsz) {
        ((float4*)out)[j] = z;
        float4 v = ((const float4*)x)[j];
        __half2 h0; h0.x = __float2half(v.x); h0.y = __float2half(v.y);
        __half2 h1; h1.x = __float2half(v.z); h1.y = __float2half(v.w);
        ((__half2*)g_xh)[2 * j]     = h0;
        ((__half2*)g_xh)[2 * j + 1] = h1;
    }
}

// ---------------- router: 1 warp per token ----------------
__global__ void router_kernel(const float* __restrict__ x, const float* __restrict__ wr) {
    int gwarp = (blockIdx.x * blockDim.x + threadIdx.x) >> 5;
    int lane = threadIdx.x & 31;
    if (gwarp >= NTOK) return;
    const float* xr = x + (size_t)gwarp * HIDDEN;
    float acc[NEXP];
#pragma unroll
    for (int e = 0; e < NEXP; e++) acc[e] = 0.f;
    for (int k = lane; k < HIDDEN; k += 32) {
        float xv = xr[k];
        const float* w = wr + (size_t)k * NEXP;
#pragma unroll
        for (int e = 0; e < NEXP; e++) acc[e] += xv * w[e];
    }
#pragma unroll
    for (int off = 16; off; off >>= 1)
#pragma unroll
        for (int e = 0; e < NEXP; e++) acc[e] += __shfl_xor_sync(0xffffffffu, acc[e], off);
    if (lane != 0) return;

    float mx = acc[0];
#pragma unroll
    for (int e = 1; e < NEXP; e++) mx = fmaxf(mx, acc[e]);
    float p[NEXP], s = 0.f;
#pragma unroll
    for (int e = 0; e < NEXP; e++) { p[e] = expf(acc[e] - mx); s += p[e]; }
    float inv = 1.f / s;
#pragma unroll
    for (int e = 0; e < NEXP; e++) p[e] *= inv;

    int i0 = 0; float v0 = p[0];
#pragma unroll
    for (int e = 1; e < NEXP; e++) if (p[e] > v0) { v0 = p[e]; i0 = e; }
    int i1 = -1; float v1 = -1.f;
#pragma unroll
    for (int e = 0; e < NEXP; e++) { if (e == i0) continue; if (p[e] > v1) { v1 = p[e]; i1 = e; } }
    float wsum = v0 + v1;
    g_topi[gwarp * 2 + 0] = i0; g_topw[gwarp * 2 + 0] = v0 / wsum;
    g_topi[gwarp * 2 + 1] = i1; g_topw[gwarp * 2 + 1] = v1 / wsum;
    atomicAdd(&g_cnt1[i0], 1);
    atomicAdd(&g_cnt2[i0], 1);
    atomicAdd(&g_cnt2[i1], 1);
#pragma unroll
    for (int e = 0; e < NEXP; e++) atomicAdd(&g_probsum[e], p[e]);
}

// ---------------- offsets + tile list + aux loss ----------------
__global__ void offsets_kernel(float* __restrict__ out, int out_size) {
    int t = threadIdx.x;
    if (t == 0) {
        int off = 0;
        for (int e = 0; e < NEXP; e++) { g_offset[e] = off; off += g_cnt2[e]; }
        g_offset[NEXP] = off;
        int idx = 0;
        for (int e = 0; e < NEXP; e++) {
            int nt = (g_cnt2[e] + BM - 1) / BM;
            int base = g_offset[e];
            for (int k = 0; k < nt; k++) { g_tile_e[idx] = e; g_tile_row[idx] = base + k * BM; idx++; }
        }
        g_ntiles = idx;
    } else if (t == 32 && out_size > NTOK * HIDDEN) {
        float aux = 0.f;
        for (int e = 0; e < NEXP; e++)
            aux += ((float)g_cnt1[e] / (float)NTOK) * (g_probsum[e] / (float)NTOK);
        out[out_size - 1] = aux * (float)NEXP;
    }
}

// ---------------- scatter ----------------
__global__ void scatter_kernel() {
    int i = blockIdx.x * blockDim.x + threadIdx.x;
    if (i >= SLOTS) return;
    int e = g_topi[i];
    int pos = atomicAdd(&g_cursor[e], 1);
    int slot = g_offset[e] + pos;
    g_tok_list[slot] = i >> 1;
    g_slot_w[slot] = g_topw[i];
}

// ---------------- W transpose + convert: [E][K][N] f32 -> [E][N][K] fp16 ----
__global__ void wconv_kernel(const float* __restrict__ W,
                             __half* __restrict__ out,
                             int K, int N) {
    __shared__ float t[32][33];
    int e = blockIdx.z;
    const float* Wb = W + (size_t)e * K * N;
    int n0 = blockIdx.x * 32, k0 = blockIdx.y * 32;
    for (int i = threadIdx.y; i < 32; i += 8)
        t[i][threadIdx.x] = Wb[(size_t)(k0 + i) * N + n0 + threadIdx.x];
    __syncthreads();
    for (int i = threadIdx.y; i < 32; i += 8) {
        float v = t[threadIdx.x][i];
        out[((size_t)e * N + n0 + i) * K + k0 + threadIdx.x] = __float2half(v);
    }
}

// ---------------- grouped fp16 mma.sync GEMM (BM=128, BN=128, BK=64) ---------
// mode 0 (GEMM1): gathered A = x, SiLU, fp16 out to hb
// mode 1 (GEMM2): A = hb, fused combine: atomicAdd(out[token], w*val)
__global__ __launch_bounds__(256, 2)
void moe_gemm(const __half* __restrict__ A,
              const __half* __restrict__ Bw,
              int K, int Nd, int mode,
              __half* __restrict__ outH, float* __restrict__ outF) {
    int tile = blockIdx.x;
    if (tile >= g_ntiles) return;
    int e = g_tile_e[tile];
    int row0 = g_tile_row[tile];
    int mcount = g_offset[e + 1] - row0;
    if (mcount > BM) mcount = BM;
    int n0 = blockIdx.y * BN;

    extern __shared__ char smem[];
    uint32_t sb = smem_u32(smem);
    int tid = threadIdx.x;
    int lane = tid & 31;
    int wid = tid >> 5;
    int warp_m = wid & 1;        // 2 -> 64 rows each
    int warp_n = wid >> 1;       // 4 -> 32 cols each

    // ---- cp.async offsets: 4 x 16B chunks per operand per thread ----
    // tile rows hold 128B (8 chunks of 16B); 1024 chunks / 256 threads = 4
    uint32_t a_src[4], a_dst[4], b_src[4];
#pragma unroll
    for (int i = 0; i < 4; i++) {
        int id = tid + i * 256;
        int row = id >> 3, c16 = id & 7;
        int srow = (mode == 0) ? g_tok_list[row0 + row] : (row0 + row);
        a_src[i] = (uint32_t)srow * (uint32_t)K + c16 * 8;
        a_dst[i] = row * STRIDE + c16 * 16;
        b_src[i] = ((uint32_t)e * (uint32_t)Nd + n0 + row) * (uint32_t)K + c16 * 8;
    }

    float acc[4][4][4];
#pragma unroll
    for (int m = 0; m < 4; m++)
#pragma unroll
        for (int n = 0; n < 4; n++)
#pragma unroll
            for (int r = 0; r < 4; r++) acc[m][n][r] = 0.f;

    // ldmatrix smem-relative offsets
    uint32_t a_rel[4], b_rel[2];
    {
        int row_a = warp_m * 64 + (lane & 15);
        int ka = (lane & 16) ? 16 : 0;
#pragma unroll
        for (int m = 0; m < 4; m++) a_rel[m] = (row_a + m * 16) * STRIDE + ka;
        int row_b = warp_n * 32 + (lane & 7) + ((lane & 16) >> 1);
        int kb = (lane & 8) * 2;
#pragma unroll
        for (int p = 0; p < 2; p++) b_rel[p] = (row_b + p * 16) * STRIDE + kb;
    }

    int nch = K / BK;   // 16 (GEMM1) or 32 (GEMM2)

    // prologue: stages 0 and 1
#pragma unroll
    for (int ps = 0; ps < 2; ps++) {
        uint32_t base = sb + ps * STAGEBYTES;
        uint32_t k0 = ps * BK;
#pragma unroll
        for (int i = 0; i < 4; i++) {
            CP_ASYNC16(base + a_dst[i],               (const char*)(A  + a_src[i] + k0));
            CP_ASYNC16(base + A_TILEBYTES + a_dst[i], (const char*)(Bw + b_src[i] + k0));
        }
        CP_COMMIT();
    }

    int slot = 0;
    for (int ch = 0; ch < nch; ch++) {
        if (ch + 1 < nch) CP_WAIT(1); else CP_WAIT(0);
        __syncthreads();

        if (ch + 2 < nch) {
            int ns = slot + 2; if (ns >= NSTAGE) ns -= NSTAGE;
            uint32_t base = sb + ns * STAGEBYTES;
            uint32_t k0 = (ch + 2) * BK;
#pragma unroll
            for (int i = 0; i < 4; i++) {
                CP_ASYNC16(base + a_dst[i],               (const char*)(A  + a_src[i] + k0));
                CP_ASYNC16(base + A_TILEBYTES + a_dst[i], (const char*)(Bw + b_src[i] + k0));
            }
            CP_COMMIT();
        }

        uint32_t Ab = sb + slot * STAGEBYTES;
        uint32_t Bb = Ab + A_TILEBYTES;

#pragma unroll
        for (int ks = 0; ks < 4; ks++) {
            uint32_t kb = ks * 32;  // 16 fp16 = 32 bytes per k-step
            uint32_t Ar[4][4], Br[2][4];
#pragma unroll
            for (int m = 0; m < 4; m++)
                LDSM_X4(Ar[m], Ab + a_rel[m] + kb);
#pragma unroll
            for (int p = 0; p < 2; p++)
                LDSM_X4(Br[p], Bb + b_rel[p] + kb);
#pragma unroll
            for (int n = 0; n < 4; n++) {
                int p = n >> 1, q = (n & 1) * 2;
                uint32_t b0 = Br[p][q], b1 = Br[p][q + 1];
#pragma unroll
                for (int m = 0; m < 4; m++)
                    MMA16816(acc[m][n], Ar[m], b0, b1);
            }
        }
        slot++; if (slot >= NSTAGE) slot = 0;
    }

    // ---- epilogue ----
    int g = lane >> 2, tig = lane & 3;
    if (mode == 0) {
#pragma unroll
        for (int m = 0; m < 4; m++) {
            int lr = warp_m * 64 + m * 16 + g;
#pragma unroll
            for (int h = 0; h < 2; h++) {
                int lrow = lr + h * 8;
                if (lrow >= mcount) continue;
                size_t grow = (size_t)(row0 + lrow);
#pragma unroll
                for (int n = 0; n < 4; n++) {
                    int col = n0 + warp_n * 32 + n * 8 + 2 * tig;
                    float f0 = acc[m][n][h * 2 + 0];
                    float f1 = acc[m][n][h * 2 + 1];
                    f0 = f0 / (1.f + expf(-f0));
                    f1 = f1 / (1.f + expf(-f1));
                    __half2 hv; hv.x = __float2half(f0); hv.y = __float2half(f1);
                    *reinterpret_cast<__half2*>(outH + grow * Nd + col) = hv;
                }
            }
        }
    } else {
#pragma unroll
        for (int m = 0; m < 4; m++) {
            int lr = warp_m * 64 + m * 16 + g;
#pragma unroll
            for (int h = 0; h < 2; h++) {
                int lrow = lr + h * 8;
                if (lrow >= mcount) continue;
                int srow = row0 + lrow;
                int token = g_tok_list[srow];
                float w = g_slot_w[srow];
                float* obase = outF + (size_t)token * HIDDEN;
#pragma unroll
                for (int n = 0; n < 4; n++) {
                    int col = n0 + warp_n * 32 + n * 8 + 2 * tig;
                    atomicAdd(obase + col,     w * acc[m][n][h * 2 + 0]);
                    atomicAdd(obase + col + 1, w * acc[m][n][h * 2 + 1]);
                }
            }
        }
    }
}

// ---------------- launch ----------------
extern "C" void kernel_launch(void* const* d_in, const int* in_sizes, int n_in,
                              void* d_out, int out_size) {
    const float* x  = (const float*)d_in[0];
    const float* wr = (const float*)d_in[1];
    const float* w1 = (const float*)d_in[2];
    const float* w2 = (const float*)d_in[3];
    float* out = (float*)d_out;

    static int configured = 0;
    if (!configured) {
        cudaFuncSetAttribute(moe_gemm, cudaFuncAttributeMaxDynamicSharedMemorySize, SMEM_TOTAL);
        configured = 1;
    }

    __half *xh, *w1t, *w2t, *hb;
    cudaGetSymbolAddress((void**)&xh,  g_xh);
    cudaGetSymbolAddress((void**)&w1t, g_w1t);
    cudaGetSymbolAddress((void**)&w2t, g_w2t);
    cudaGetSymbolAddress((void**)&hb,  g_hb);

    prep_kernel<<<512, 256>>>(x, out);
    router_kernel<<<(NTOK * 32 + 255) / 256, 256>>>(x, wr);
    offsets_kernel<<<1, 64>>>(out, out_size);
    scatter_kernel<<<(SLOTS + 255) / 256, 256>>>();

    wconv_kernel<<<dim3(INTER / 32, HIDDEN / 32, NEXP), dim3(32, 8)>>>(w1, w1t, HIDDEN, INTER);
    wconv_kernel<<<dim3(HIDDEN / 32, INTER / 32, NEXP), dim3(32, 8)>>>(w2, w2t, INTER, HIDDEN);

    // GEMM1: hb[slot, INTER] = silu(gather(x) @ W1), fp16
    moe_gemm<<<dim3(MAX_TILES, INTER / BN), 256, SMEM_TOTAL>>>(
        xh, w1t, HIDDEN, INTER, 0, hb, (float*)0);
    // GEMM2 + fused combine: out[token] += w * (hb @ W2)
    moe_gemm<<<dim3(MAX_TILES, HIDDEN / BN), 256, SMEM_TOTAL>>>(
        hb, w2t, INTER, HIDDEN, 1, (__half*)0, out);
}

// round 14
// speedup vs baseline: 1.3352x; 1.0775x over previous
#include <cuda_runtime.h>
#include <cuda_fp16.h>
#include <math.h>
#include <stdint.h>

#define HIDDEN 1024
#define INTER  2048
#define NEXP   8
#define NTOK   8192
#define SLOTS  (NTOK * 2)          // 16384
#define BM 128
#define BN 128
#define BK 64
#define SLOTS_PAD (SLOTS + BM)
#define MAX_TILES (SLOTS / BM + NEXP)  // 136

#define STRIDE_A 144                  // 64 fp16 = 128B + 16B pad
#define STRIDE_B 272                  // 128 fp16 = 256B + 16B pad
#define A_TILEBYTES (BM * STRIDE_A)   // 18432
#define B_TILEBYTES (BK * STRIDE_B)   // 17408
#define STAGEBYTES (A_TILEBYTES + B_TILEBYTES)  // 35840
#define NSTAGE 3
#define SMEM_TOTAL (NSTAGE * STAGEBYTES)        // 107520/CTA, 2 CTAs = 215KB

// ---------------- device scratch (static, no allocations) ----------------
__device__ int   g_cnt2[NEXP];
__device__ int   g_cnt1[NEXP];
__device__ float g_probsum[NEXP];
__device__ int   g_offset[NEXP + 1];
__device__ int   g_cursor[NEXP];
__device__ int   g_tile_e[MAX_TILES];
__device__ int   g_tile_row[MAX_TILES];
__device__ int   g_ntiles;
__device__ int   g_tok_list[SLOTS_PAD];
__device__ float g_slot_w[SLOTS_PAD];
__device__ float g_topw[SLOTS];
__device__ int   g_topi[SLOTS];

__device__ __half g_xh[NTOK * HIDDEN];
__device__ __half g_w1h[NEXP * HIDDEN * INTER];   // [E][K=H][N=I] fp16 (same layout as w1)
__device__ __half g_w2h[NEXP * INTER * HIDDEN];   // [E][K=I][N=H] fp16 (same layout as w2)
__device__ __half g_hb[(size_t)SLOTS_PAD * INTER];

// ---------------- PTX helpers ----------------
__device__ __forceinline__ uint32_t smem_u32(const void* p) {
    uint32_t a;
    asm("{ .reg .u64 t; cvta.to.shared.u64 t, %1; cvt.u32.u64 %0, t; }" : "=r"(a) : "l"(p));
    return a;
}
#define CP_ASYNC16(dst, src) \
    asm volatile("cp.async.cg.shared.global [%0], [%1], 16;" :: "r"(dst), "l"(src) : "memory")
#define CP_COMMIT() asm volatile("cp.async.commit_group;" ::: "memory")
#define CP_WAIT(n)  asm volatile("cp.async.wait_group %0;" :: "n"(n) : "memory")

#define LDSM_X4(r, a) \
    asm volatile("ldmatrix.sync.aligned.m8n8.x4.shared.b16 {%0,%1,%2,%3}, [%4];" \
        : "=r"((r)[0]), "=r"((r)[1]), "=r"((r)[2]), "=r"((r)[3]) : "r"(a))

#define LDSM_X4_T(r, a) \
    asm volatile("ldmatrix.sync.aligned.m8n8.x4.trans.shared.b16 {%0,%1,%2,%3}, [%4];" \
        : "=r"((r)[0]), "=r"((r)[1]), "=r"((r)[2]), "=r"((r)[3]) : "r"(a))

#define MMA16816(c, a, b0, b1) \
    asm volatile("mma.sync.aligned.m16n8k16.row.col.f32.f16.f16.f32 " \
        "{%0,%1,%2,%3}, {%4,%5,%6,%7}, {%8,%9}, {%0,%1,%2,%3};" \
        : "+f"((c)[0]), "+f"((c)[1]), "+f"((c)[2]), "+f"((c)[3]) \
        : "r"((a)[0]), "r"((a)[1]), "r"((a)[2]), "r"((a)[3]), "r"(b0), "r"(b1))

// ---------------- fused prep: counters, pads, zero out, convert x/W1/W2 ----
__global__ void prep_kernel(const float* __restrict__ x,
                            const float* __restrict__ w1,
                            const float* __restrict__ w2,
                            float* __restrict__ out) {
    int gid = blockIdx.x * blockDim.x + threadIdx.x;
    int gsz = gridDim.x * blockDim.x;
    if (gid < NEXP) { g_cnt1[gid] = 0; g_cnt2[gid] = 0; g_cursor[gid] = 0; g_probsum[gid] = 0.f; }
    for (int j = gid; j < SLOTS_PAD; j += gsz) { g_tok_list[j] = 0; g_slot_w[j] = 0.f; }

    float4 z; z.x = z.y = z.z = z.w = 0.f;
    for (int j = gid; j < NTOK * HIDDEN / 4; j += gsz) {
        ((float4*)out)[j] = z;
        float4 v = ((const float4*)x)[j];
        __half2 h0; h0.x = __float2half(v.x); h0.y = __float2half(v.y);
        __half2 h1; h1.x = __float2half(v.z); h1.y = __float2half(v.w);
        ((__half2*)g_xh)[2 * j]     = h0;
        ((__half2*)g_xh)[2 * j + 1] = h1;
    }
    // W1: straight convert (layout already [E][K][N])
    for (int j = gid; j < NEXP * HIDDEN * INTER / 4; j += gsz) {
        float4 v = ((const float4*)w1)[j];
        __half2 h0; h0.x = __float2half(v.x); h0.y = __float2half(v.y);
        __half2 h1; h1.x = __float2half(v.z); h1.y = __float2half(v.w);
        ((__half2*)g_w1h)[2 * j]     = h0;
        ((__half2*)g_w1h)[2 * j + 1] = h1;
    }
    // W2: straight convert
    for (int j = gid; j < NEXP * INTER * HIDDEN / 4; j += gsz) {
        float4 v = ((const float4*)w2)[j];
        __half2 h0; h0.x = __float2half(v.x); h0.y = __float2half(v.y);
        __half2 h1; h1.x = __float2half(v.z); h1.y = __float2half(v.w);
        ((__half2*)g_w2h)[2 * j]     = h0;
        ((__half2*)g_w2h)[2 * j + 1] = h1;
    }
}

// ---------------- router: 1 warp per token ----------------
__global__ void router_kernel(const float* __restrict__ x, const float* __restrict__ wr) {
    int gwarp = (blockIdx.x * blockDim.x + threadIdx.x) >> 5;
    int lane = threadIdx.x & 31;
    if (gwarp >= NTOK) return;
    const float* xr = x + (size_t)gwarp * HIDDEN;
    float acc[NEXP];
#pragma unroll
    for (int e = 0; e < NEXP; e++) acc[e] = 0.f;
    for (int k = lane; k < HIDDEN; k += 32) {
        float xv = xr[k];
        const float* w = wr + (size_t)k * NEXP;
#pragma unroll
        for (int e = 0; e < NEXP; e++) acc[e] += xv * w[e];
    }
#pragma unroll
    for (int off = 16; off; off >>= 1)
#pragma unroll
        for (int e = 0; e < NEXP; e++) acc[e] += __shfl_xor_sync(0xffffffffu, acc[e], off);
    if (lane != 0) return;

    float mx = acc[0];
#pragma unroll
    for (int e = 1; e < NEXP; e++) mx = fmaxf(mx, acc[e]);
    float p[NEXP], s = 0.f;
#pragma unroll
    for (int e = 0; e < NEXP; e++) { p[e] = expf(acc[e] - mx); s += p[e]; }
    float inv = 1.f / s;
#pragma unroll
    for (int e = 0; e < NEXP; e++) p[e] *= inv;

    int i0 = 0; float v0 = p[0];
#pragma unroll
    for (int e = 1; e < NEXP; e++) if (p[e] > v0) { v0 = p[e]; i0 = e; }
    int i1 = -1; float v1 = -1.f;
#pragma unroll
    for (int e = 0; e < NEXP; e++) { if (e == i0) continue; if (p[e] > v1) { v1 = p[e]; i1 = e; } }
    float wsum = v0 + v1;
    g_topi[gwarp * 2 + 0] = i0; g_topw[gwarp * 2 + 0] = v0 / wsum;
    g_topi[gwarp * 2 + 1] = i1; g_topw[gwarp * 2 + 1] = v1 / wsum;
    atomicAdd(&g_cnt1[i0], 1);
    atomicAdd(&g_cnt2[i0], 1);
    atomicAdd(&g_cnt2[i1], 1);
#pragma unroll
    for (int e = 0; e < NEXP; e++) atomicAdd(&g_probsum[e], p[e]);
}

// ---------------- offsets + tile list + aux loss ----------------
__global__ void offsets_kernel(float* __restrict__ out, int out_size) {
    int t = threadIdx.x;
    if (t == 0) {
        int off = 0;
        for (int e = 0; e < NEXP; e++) { g_offset[e] = off; off += g_cnt2[e]; }
        g_offset[NEXP] = off;
        int idx = 0;
        for (int e = 0; e < NEXP; e++) {
            int nt = (g_cnt2[e] + BM - 1) / BM;
            int base = g_offset[e];
            for (int k = 0; k < nt; k++) { g_tile_e[idx] = e; g_tile_row[idx] = base + k * BM; idx++; }
        }
        g_ntiles = idx;
    } else if (t == 32 && out_size > NTOK * HIDDEN) {
        float aux = 0.f;
        for (int e = 0; e < NEXP; e++)
            aux += ((float)g_cnt1[e] / (float)NTOK) * (g_probsum[e] / (float)NTOK);
        out[out_size - 1] = aux * (float)NEXP;
    }
}

// ---------------- scatter ----------------
__global__ void scatter_kernel() {
    int i = blockIdx.x * blockDim.x + threadIdx.x;
    if (i >= SLOTS) return;
    int e = g_topi[i];
    int pos = atomicAdd(&g_cursor[e], 1);
    int slot = g_offset[e] + pos;
    g_tok_list[slot] = i >> 1;
    g_slot_w[slot] = g_topw[i];
}

// ---------------- grouped fp16 mma.sync GEMM (128x128, BK=64, trans-B) ------
// B stored [E][K][N] fp16 (natural layout); B fragments via ldmatrix.trans.
// mode 0 (GEMM1): gathered A = x, SiLU, fp16 out to hb
// mode 1 (GEMM2): A = hb, fused combine: atomicAdd(out[token], w*val)
__global__ __launch_bounds__(256, 2)
void moe_gemm(const __half* __restrict__ A,
              const __half* __restrict__ Bw,
              int K, int Nd, int mode,
              __half* __restrict__ outH, float* __restrict__ outF) {
    int tile = blockIdx.x;
    if (tile >= g_ntiles) return;
    int e = g_tile_e[tile];
    int row0 = g_tile_row[tile];
    int mcount = g_offset[e + 1] - row0;
    if (mcount > BM) mcount = BM;
    int n0 = blockIdx.y * BN;

    extern __shared__ char smem[];
    uint32_t sb = smem_u32(smem);
    int tid = threadIdx.x;
    int lane = tid & 31;
    int wid = tid >> 5;
    int warp_m = wid & 1;        // 2 -> 64 rows each
    int warp_n = wid >> 1;       // 4 -> 32 cols each

    // ---- cp.async offsets ----
    // A tile: 128 rows x 8 chunks (16B) = 1024 chunks -> 4/thread
    // B tile: 64 k-rows x 16 chunks = 1024 chunks -> 4/thread
    uint32_t a_src[4], a_dst[4], b_src[4], b_dst[4];
#pragma unroll
    for (int i = 0; i < 4; i++) {
        int id = tid + i * 256;
        int arow = id >> 3, ac16 = id & 7;
        int srow = (mode == 0) ? g_tok_list[row0 + arow] : (row0 + arow);
        a_src[i] = (uint32_t)srow * (uint32_t)K + ac16 * 8;
        a_dst[i] = arow * STRIDE_A + ac16 * 16;
        int brow = id >> 4, bc16 = id & 15;      // k-row, 16B chunk in n
        b_src[i] = ((uint32_t)e * (uint32_t)K + brow) * (uint32_t)Nd + n0 + bc16 * 8;
        b_dst[i] = brow * STRIDE_B + bc16 * 16;
    }

    float acc[4][4][4];
#pragma unroll
    for (int m = 0; m < 4; m++)
#pragma unroll
        for (int n = 0; n < 4; n++)
#pragma unroll
            for (int r = 0; r < 4; r++) acc[m][n][r] = 0.f;

    // ldmatrix smem-relative offsets
    uint32_t a_rel[4], b_rel[2];
    {
        int row_a = warp_m * 64 + (lane & 15);
        int ka = (lane & 16) ? 16 : 0;
#pragma unroll
        for (int m = 0; m < 4; m++) a_rel[m] = (row_a + m * 16) * STRIDE_A + ka;
        // trans-B: lanes 0-15 -> k-rows (lane&15) at n_off; lanes 16-31 -> same rows, n_off+8
        int krow = lane & 15;
        int nadd = (lane & 16) >> 1;   // +8 cols for upper half
#pragma unroll
        for (int p = 0; p < 2; p++)
            b_rel[p] = krow * STRIDE_B + (warp_n * 32 + p * 16 + nadd) * 2;
    }

    int nch = K / BK;   // 16 (GEMM1) or 32 (GEMM2)

    // prologue: stages 0 and 1
#pragma unroll
    for (int ps = 0; ps < 2; ps++) {
        uint32_t base = sb + ps * STAGEBYTES;
        uint32_t k0 = ps * BK;
#pragma unroll
        for (int i = 0; i < 4; i++) {
            CP_ASYNC16(base + a_dst[i],               (const char*)(A  + a_src[i] + k0));
            CP_ASYNC16(base + A_TILEBYTES + b_dst[i], (const char*)(Bw + b_src[i] + k0 * (uint32_t)Nd));
        }
        CP_COMMIT();
    }

    int slot = 0;
    for (int ch = 0; ch < nch; ch++) {
        if (ch + 1 < nch) CP_WAIT(1); else CP_WAIT(0);
        __syncthreads();

        if (ch + 2 < nch) {
            int ns = slot + 2; if (ns >= NSTAGE) ns -= NSTAGE;
            uint32_t base = sb + ns * STAGEBYTES;
            uint32_t k0 = (ch + 2) * BK;
#pragma unroll
            for (int i = 0; i < 4; i++) {
                CP_ASYNC16(base + a_dst[i],               (const char*)(A  + a_src[i] + k0));
                CP_ASYNC16(base + A_TILEBYTES + b_dst[i], (const char*)(Bw + b_src[i] + k0 * (uint32_t)Nd));
            }
            CP_COMMIT();
        }

        uint32_t Ab = sb + slot * STAGEBYTES;
        uint32_t Bb = Ab + A_TILEBYTES;

#pragma unroll
        for (int ks = 0; ks < 4; ks++) {
            uint32_t Ar[4][4], Br[2][4];
#pragma unroll
            for (int m = 0; m < 4; m++)
                LDSM_X4(Ar[m], Ab + a_rel[m] + ks * 32);
#pragma unroll
            for (int p = 0; p < 2; p++)
                LDSM_X4_T(Br[p], Bb + b_rel[p] + ks * 16 * STRIDE_B);
#pragma unroll
            for (int n = 0; n < 4; n++) {
                int p = n >> 1, q = (n & 1) * 2;
                uint32_t b0 = Br[p][q], b1 = Br[p][q + 1];
#pragma unroll
                for (int m = 0; m < 4; m++)
                    MMA16816(acc[m][n], Ar[m], b0, b1);
            }
        }
        slot++; if (slot >= NSTAGE) slot = 0;
    }

    // ---- epilogue ----
    int g = lane >> 2, tig = lane & 3;
    if (mode == 0) {
#pragma unroll
        for (int m = 0; m < 4; m++) {
            int lr = warp_m * 64 + m * 16 + g;
#pragma unroll
            for (int h = 0; h < 2; h++) {
                int lrow = lr + h * 8;
                if (lrow >= mcount) continue;
                size_t grow = (size_t)(row0 + lrow);
#pragma unroll
                for (int n = 0; n < 4; n++) {
                    int col = n0 + warp_n * 32 + n * 8 + 2 * tig;
                    float f0 = acc[m][n][h * 2 + 0];
                    float f1 = acc[m][n][h * 2 + 1];
                    f0 = f0 / (1.f + expf(-f0));
                    f1 = f1 / (1.f + expf(-f1));
                    __half2 hv; hv.x = __float2half(f0); hv.y = __float2half(f1);
                    *reinterpret_cast<__half2*>(outH + grow * Nd + col) = hv;
                }
            }
        }
    } else {
#pragma unroll
        for (int m = 0; m < 4; m++) {
            int lr = warp_m * 64 + m * 16 + g;
#pragma unroll
            for (int h = 0; h < 2; h++) {
                int lrow = lr + h * 8;
                if (lrow >= mcount) continue;
                int srow = row0 + lrow;
                int token = g_tok_list[srow];
                float w = g_slot_w[srow];
                float* obase = outF + (size_t)token * HIDDEN;
#pragma unroll
                for (int n = 0; n < 4; n++) {
                    int col = n0 + warp_n * 32 + n * 8 + 2 * tig;
                    atomicAdd(obase + col,     w * acc[m][n][h * 2 + 0]);
                    atomicAdd(obase + col + 1, w * acc[m][n][h * 2 + 1]);
                }
            }
        }
    }
}

// ---------------- launch ----------------
extern "C" void kernel_launch(void* const* d_in, const int* in_sizes, int n_in,
                              void* d_out, int out_size) {
    const float* x  = (const float*)d_in[0];
    const float* wr = (const float*)d_in[1];
    const float* w1 = (const float*)d_in[2];
    const float* w2 = (const float*)d_in[3];
    float* out = (float*)d_out;

    static int configured = 0;
    if (!configured) {
        cudaFuncSetAttribute(moe_gemm, cudaFuncAttributeMaxDynamicSharedMemorySize, SMEM_TOTAL);
        configured = 1;
    }

    __half *xh, *w1h, *w2h, *hb;
    cudaGetSymbolAddress((void**)&xh,  g_xh);
    cudaGetSymbolAddress((void**)&w1h, g_w1h);
    cudaGetSymbolAddress((void**)&w2h, g_w2h);
    cudaGetSymbolAddress((void**)&hb,  g_hb);

    prep_kernel<<<512, 256>>>(x, w1, w2, out);
    router_kernel<<<(NTOK * 32 + 255) / 256, 256>>>(x, wr);
    offsets_kernel<<<1, 64>>>(out, out_size);
    scatter_kernel<<<(SLOTS + 255) / 256, 256>>>();

    // GEMM1: hb[slot, INTER] = silu(gather(x) @ W1), fp16   (K=HIDDEN, N=INTER)
    moe_gemm<<<dim3(MAX_TILES, INTER / BN), 256, SMEM_TOTAL>>>(
        xh, w1h, HIDDEN, INTER, 0, hb, (float*)0);
    // GEMM2 + fused combine: out[token] += w * (hb @ W2)    (K=INTER, N=HIDDEN)
    moe_gemm<<<dim3(MAX_TILES, HIDDEN / BN), 256, SMEM_TOTAL>>>(
        hb, w2h, INTER, HIDDEN, 1, (__half*)0, out);
}

// round 15
// speedup vs baseline: 1.4129x; 1.0582x over previous
#include <cuda_runtime.h>
#include <cuda_fp16.h>
#include <math.h>
#include <stdint.h>

#define HIDDEN 1024
#define INTER  2048
#define NEXP   8
#define NTOK   8192
#define SLOTS  (NTOK * 2)          // 16384
#define BM 128
#define BN 128
#define BK 64
#define SLOTS_PAD (SLOTS + BM)
#define MAX_TILES (SLOTS / BM + NEXP)  // 136

#define STRIDE_A 144                  // 64 fp16 = 128B + 16B pad
#define STRIDE_B 272                  // 128 fp16 = 256B + 16B pad
#define A_TILEBYTES (BM * STRIDE_A)   // 18432
#define B_TILEBYTES (BK * STRIDE_B)   // 17408
#define STAGEBYTES (A_TILEBYTES + B_TILEBYTES)  // 35840
#define NSTAGE 3
#define SMEM_TOTAL (NSTAGE * STAGEBYTES)        // 107520/CTA, 2 CTAs = 215KB

// ---------------- device scratch (static, no allocations) ----------------
__device__ int   g_cnt2[NEXP];
__device__ int   g_cnt1[NEXP];
__device__ float g_probsum[NEXP];
__device__ int   g_offset[NEXP + 1];
__device__ int   g_cursor[NEXP];
__device__ int   g_tile_e[MAX_TILES];
__device__ int   g_tile_row[MAX_TILES];
__device__ int   g_ntiles;
__device__ int   g_tok_list[SLOTS_PAD];
__device__ float g_slot_w[SLOTS_PAD];
__device__ float g_topw[SLOTS];
__device__ int   g_topi[SLOTS];

__device__ __half g_xh[NTOK * HIDDEN];
__device__ __half g_w1h[NEXP * HIDDEN * INTER];   // [E][K=H][N=I] fp16
__device__ __half g_w2h[NEXP * INTER * HIDDEN];   // [E][K=I][N=H] fp16
__device__ __half g_hb[(size_t)SLOTS_PAD * INTER];

// ---------------- PTX helpers ----------------
__device__ __forceinline__ uint32_t smem_u32(const void* p) {
    uint32_t a;
    asm("{ .reg .u64 t; cvta.to.shared.u64 t, %1; cvt.u32.u64 %0, t; }" : "=r"(a) : "l"(p));
    return a;
}
#define CP_ASYNC16(dst, src) \
    asm volatile("cp.async.cg.shared.global [%0], [%1], 16;" :: "r"(dst), "l"(src) : "memory")
#define CP_COMMIT() asm volatile("cp.async.commit_group;" ::: "memory")
#define CP_WAIT(n)  asm volatile("cp.async.wait_group %0;" :: "n"(n) : "memory")

#define LDSM_X4(r, a) \
    asm volatile("ldmatrix.sync.aligned.m8n8.x4.shared.b16 {%0,%1,%2,%3}, [%4];" \
        : "=r"((r)[0]), "=r"((r)[1]), "=r"((r)[2]), "=r"((r)[3]) : "r"(a))

#define LDSM_X4_T(r, a) \
    asm volatile("ldmatrix.sync.aligned.m8n8.x4.trans.shared.b16 {%0,%1,%2,%3}, [%4];" \
        : "=r"((r)[0]), "=r"((r)[1]), "=r"((r)[2]), "=r"((r)[3]) : "r"(a))

#define MMA16816(c, a, b0, b1) \
    asm volatile("mma.sync.aligned.m16n8k16.row.col.f32.f16.f16.f32 " \
        "{%0,%1,%2,%3}, {%4,%5,%6,%7}, {%8,%9}, {%0,%1,%2,%3};" \
        : "+f"((c)[0]), "+f"((c)[1]), "+f"((c)[2]), "+f"((c)[3]) \
        : "r"((a)[0]), "r"((a)[1]), "r"((a)[2]), "r"((a)[3]), "r"(b0), "r"(b1))

// ---------------- prep A: counters, pads, zero out, convert x + W1 ----------
__global__ void prep_main_kernel(const float* __restrict__ x,
                                 const float* __restrict__ w1,
                                 float* __restrict__ out) {
    int gid = blockIdx.x * blockDim.x + threadIdx.x;
    int gsz = gridDim.x * blockDim.x;
    if (gid < NEXP) { g_cnt1[gid] = 0; g_cnt2[gid] = 0; g_cursor[gid] = 0; g_probsum[gid] = 0.f; }
    for (int j = gid; j < SLOTS_PAD; j += gsz) { g_tok_list[j] = 0; g_slot_w[j] = 0.f; }

    float4 z; z.x = z.y = z.z = z.w = 0.f;
    for (int j = gid; j < NTOK * HIDDEN / 4; j += gsz) {
        ((float4*)out)[j] = z;
        float4 v = ((const float4*)x)[j];
        __half2 h0; h0.x = __float2half(v.x); h0.y = __float2half(v.y);
        __half2 h1; h1.x = __float2half(v.z); h1.y = __float2half(v.w);
        ((__half2*)g_xh)[2 * j]     = h0;
        ((__half2*)g_xh)[2 * j + 1] = h1;
    }
    for (int j = gid; j < NEXP * HIDDEN * INTER / 4; j += gsz) {
        float4 v = ((const float4*)w1)[j];
        __half2 h0; h0.x = __float2half(v.x); h0.y = __float2half(v.y);
        __half2 h1; h1.x = __float2half(v.z); h1.y = __float2half(v.w);
        ((__half2*)g_w1h)[2 * j]     = h0;
        ((__half2*)g_w1h)[2 * j + 1] = h1;
    }
}

// ---------------- prep B: convert W2 (only needed before GEMM2) -------------
__global__ void prep_w2_kernel(const float* __restrict__ w2) {
    int gid = blockIdx.x * blockDim.x + threadIdx.x;
    int gsz = gridDim.x * blockDim.x;
    for (int j = gid; j < NEXP * INTER * HIDDEN / 4; j += gsz) {
        float4 v = ((const float4*)w2)[j];
        __half2 h0; h0.x = __float2half(v.x); h0.y = __float2half(v.y);
        __half2 h1; h1.x = __float2half(v.z); h1.y = __float2half(v.w);
        ((__half2*)g_w2h)[2 * j]     = h0;
        ((__half2*)g_w2h)[2 * j + 1] = h1;
    }
}

// ---------------- router: 1 warp per token ----------------
__global__ void router_kernel(const float* __restrict__ x, const float* __restrict__ wr) {
    int gwarp = (blockIdx.x * blockDim.x + threadIdx.x) >> 5;
    int lane = threadIdx.x & 31;
    if (gwarp >= NTOK) return;
    const float* xr = x + (size_t)gwarp * HIDDEN;
    float acc[NEXP];
#pragma unroll
    for (int e = 0; e < NEXP; e++) acc[e] = 0.f;
    for (int k = lane; k < HIDDEN; k += 32) {
        float xv = xr[k];
        const float* w = wr + (size_t)k * NEXP;
#pragma unroll
        for (int e = 0; e < NEXP; e++) acc[e] += xv * w[e];
    }
#pragma unroll
    for (int off = 16; off; off >>= 1)
#pragma unroll
        for (int e = 0; e < NEXP; e++) acc[e] += __shfl_xor_sync(0xffffffffu, acc[e], off);
    if (lane != 0) return;

    float mx = acc[0];
#pragma unroll
    for (int e = 1; e < NEXP; e++) mx = fmaxf(mx, acc[e]);
    float p[NEXP], s = 0.f;
#pragma unroll
    for (int e = 0; e < NEXP; e++) { p[e] = expf(acc[e] - mx); s += p[e]; }
    float inv = 1.f / s;
#pragma unroll
    for (int e = 0; e < NEXP; e++) p[e] *= inv;

    int i0 = 0; float v0 = p[0];
#pragma unroll
    for (int e = 1; e < NEXP; e++) if (p[e] > v0) { v0 = p[e]; i0 = e; }
    int i1 = -1; float v1 = -1.f;
#pragma unroll
    for (int e = 0; e < NEXP; e++) { if (e == i0) continue; if (p[e] > v1) { v1 = p[e]; i1 = e; } }
    float wsum = v0 + v1;
    g_topi[gwarp * 2 + 0] = i0; g_topw[gwarp * 2 + 0] = v0 / wsum;
    g_topi[gwarp * 2 + 1] = i1; g_topw[gwarp * 2 + 1] = v1 / wsum;
    atomicAdd(&g_cnt1[i0], 1);
    atomicAdd(&g_cnt2[i0], 1);
    atomicAdd(&g_cnt2[i1], 1);
#pragma unroll
    for (int e = 0; e < NEXP; e++) atomicAdd(&g_probsum[e], p[e]);
}

// ---------------- offsets + tile list + aux loss ----------------
__global__ void offsets_kernel(float* __restrict__ out, int out_size) {
    int t = threadIdx.x;
    if (t == 0) {
        int off = 0;
        for (int e = 0; e < NEXP; e++) { g_offset[e] = off; off += g_cnt2[e]; }
        g_offset[NEXP] = off;
        int idx = 0;
        for (int e = 0; e < NEXP; e++) {
            int nt = (g_cnt2[e] + BM - 1) / BM;
            int base = g_offset[e];
            for (int k = 0; k < nt; k++) { g_tile_e[idx] = e; g_tile_row[idx] = base + k * BM; idx++; }
        }
        g_ntiles = idx;
    } else if (t == 32 && out_size > NTOK * HIDDEN) {
        float aux = 0.f;
        for (int e = 0; e < NEXP; e++)
            aux += ((float)g_cnt1[e] / (float)NTOK) * (g_probsum[e] / (float)NTOK);
        out[out_size - 1] = aux * (float)NEXP;
    }
}

// ---------------- scatter ----------------
__global__ void scatter_kernel() {
    int i = blockIdx.x * blockDim.x + threadIdx.x;
    if (i >= SLOTS) return;
    int e = g_topi[i];
    int pos = atomicAdd(&g_cursor[e], 1);
    int slot = g_offset[e] + pos;
    g_tok_list[slot] = i >> 1;
    g_slot_w[slot] = g_topw[i];
}

// ---------------- grouped fp16 mma.sync GEMM (128x128, BK=64, trans-B) ------
__global__ __launch_bounds__(256, 2)
void moe_gemm(const __half* __restrict__ A,
              const __half* __restrict__ Bw,
              int K, int Nd, int mode,
              __half* __restrict__ outH, float* __restrict__ outF) {
    int tile = blockIdx.x;
    if (tile >= g_ntiles) return;
    int e = g_tile_e[tile];
    int row0 = g_tile_row[tile];
    int mcount = g_offset[e + 1] - row0;
    if (mcount > BM) mcount = BM;
    int n0 = blockIdx.y * BN;

    extern __shared__ char smem[];
    uint32_t sb = smem_u32(smem);
    int tid = threadIdx.x;
    int lane = tid & 31;
    int wid = tid >> 5;
    int warp_m = wid & 1;
    int warp_n = wid >> 1;

    uint32_t a_src[4], a_dst[4], b_src[4], b_dst[4];
#pragma unroll
    for (int i = 0; i < 4; i++) {
        int id = tid + i * 256;
        int arow = id >> 3, ac16 = id & 7;
        int srow = (mode == 0) ? g_tok_list[row0 + arow] : (row0 + arow);
        a_src[i] = (uint32_t)srow * (uint32_t)K + ac16 * 8;
        a_dst[i] = arow * STRIDE_A + ac16 * 16;
        int brow = id >> 4, bc16 = id & 15;
        b_src[i] = ((uint32_t)e * (uint32_t)K + brow) * (uint32_t)Nd + n0 + bc16 * 8;
        b_dst[i] = brow * STRIDE_B + bc16 * 16;
    }

    float acc[4][4][4];
#pragma unroll
    for (int m = 0; m < 4; m++)
#pragma unroll
        for (int n = 0; n < 4; n++)
#pragma unroll
            for (int r = 0; r < 4; r++) acc[m][n][r] = 0.f;

    uint32_t a_rel[4], b_rel[2];
    {
        int row_a = warp_m * 64 + (lane & 15);
        int ka = (lane & 16) ? 16 : 0;
#pragma unroll
        for (int m = 0; m < 4; m++) a_rel[m] = (row_a + m * 16) * STRIDE_A + ka;
        int krow = lane & 15;
        int nadd = (lane & 16) >> 1;
#pragma unroll
        for (int p = 0; p < 2; p++)
            b_rel[p] = krow * STRIDE_B + (warp_n * 32 + p * 16 + nadd) * 2;
    }

    int nch = K / BK;

#pragma unroll
    for (int ps = 0; ps < 2; ps++) {
        uint32_t base = sb + ps * STAGEBYTES;
        uint32_t k0 = ps * BK;
#pragma unroll
        for (int i = 0; i < 4; i++) {
            CP_ASYNC16(base + a_dst[i],               (const char*)(A  + a_src[i] + k0));
            CP_ASYNC16(base + A_TILEBYTES + b_dst[i], (const char*)(Bw + b_src[i] + k0 * (uint32_t)Nd));
        }
        CP_COMMIT();
    }

    int slot = 0;
    for (int ch = 0; ch < nch; ch++) {
        if (ch + 1 < nch) CP_WAIT(1); else CP_WAIT(0);
        __syncthreads();

        if (ch + 2 < nch) {
            int ns = slot + 2; if (ns >= NSTAGE) ns -= NSTAGE;
            uint32_t base = sb + ns * STAGEBYTES;
            uint32_t k0 = (ch + 2) * BK;
#pragma unroll
            for (int i = 0; i < 4; i++) {
                CP_ASYNC16(base + a_dst[i],               (const char*)(A  + a_src[i] + k0));
                CP_ASYNC16(base + A_TILEBYTES + b_dst[i], (const char*)(Bw + b_src[i] + k0 * (uint32_t)Nd));
            }
            CP_COMMIT();
        }

        uint32_t Ab = sb + slot * STAGEBYTES;
        uint32_t Bb = Ab + A_TILEBYTES;

#pragma unroll
        for (int ks = 0; ks < 4; ks++) {
            uint32_t Ar[4][4], Br[2][4];
#pragma unroll
            for (int m = 0; m < 4; m++)
                LDSM_X4(Ar[m], Ab + a_rel[m] + ks * 32);
#pragma unroll
            for (int p = 0; p < 2; p++)
                LDSM_X4_T(Br[p], Bb + b_rel[p] + ks * 16 * STRIDE_B);
#pragma unroll
            for (int n = 0; n < 4; n++) {
                int p = n >> 1, q = (n & 1) * 2;
                uint32_t b0 = Br[p][q], b1 = Br[p][q + 1];
#pragma unroll
                for (int m = 0; m < 4; m++)
                    MMA16816(acc[m][n], Ar[m], b0, b1);
            }
        }
        slot++; if (slot >= NSTAGE) slot = 0;
    }

    int g = lane >> 2, tig = lane & 3;
    if (mode == 0) {
#pragma unroll
        for (int m = 0; m < 4; m++) {
            int lr = warp_m * 64 + m * 16 + g;
#pragma unroll
            for (int h = 0; h < 2; h++) {
                int lrow = lr + h * 8;
                if (lrow >= mcount) continue;
                size_t grow = (size_t)(row0 + lrow);
#pragma unroll
                for (int n = 0; n < 4; n++) {
                    int col = n0 + warp_n * 32 + n * 8 + 2 * tig;
                    float f0 = acc[m][n][h * 2 + 0];
                    float f1 = acc[m][n][h * 2 + 1];
                    f0 = f0 / (1.f + expf(-f0));
                    f1 = f1 / (1.f + expf(-f1));
                    __half2 hv; hv.x = __float2half(f0); hv.y = __float2half(f1);
                    *reinterpret_cast<__half2*>(outH + grow * Nd + col) = hv;
                }
            }
        }
    } else {
#pragma unroll
        for (int m = 0; m < 4; m++) {
            int lr = warp_m * 64 + m * 16 + g;
#pragma unroll
            for (int h = 0; h < 2; h++) {
                int lrow = lr + h * 8;
                if (lrow >= mcount) continue;
                int srow = row0 + lrow;
                int token = g_tok_list[srow];
                float w = g_slot_w[srow];
                float* obase = outF + (size_t)token * HIDDEN;
#pragma unroll
                for (int n = 0; n < 4; n++) {
                    int col = n0 + warp_n * 32 + n * 8 + 2 * tig;
                    atomicAdd(obase + col,     w * acc[m][n][h * 2 + 0]);
                    atomicAdd(obase + col + 1, w * acc[m][n][h * 2 + 1]);
                }
            }
        }
    }
}

// ---------------- launch (forked-stream graph) ----------------
extern "C" void kernel_launch(void* const* d_in, const int* in_sizes, int n_in,
                              void* d_out, int out_size) {
    const float* x  = (const float*)d_in[0];
    const float* wr = (const float*)d_in[1];
    const float* w1 = (const float*)d_in[2];
    const float* w2 = (const float*)d_in[3];
    float* out = (float*)d_out;

    static cudaStream_t s1 = 0, s2 = 0;
    static cudaEvent_t e_root = 0, e_prep = 0, e_w2 = 0;
    static int configured = 0;
    if (!configured) {
        cudaFuncSetAttribute(moe_gemm, cudaFuncAttributeMaxDynamicSharedMemorySize, SMEM_TOTAL);
        cudaStreamCreateWithFlags(&s1, cudaStreamNonBlocking);
        cudaStreamCreateWithFlags(&s2, cudaStreamNonBlocking);
        cudaEventCreateWithFlags(&e_root, cudaEventDisableTiming);
        cudaEventCreateWithFlags(&e_prep, cudaEventDisableTiming);
        cudaEventCreateWithFlags(&e_w2, cudaEventDisableTiming);
        configured = 1;
    }

    __half *xh, *w1h, *w2h, *hb;
    cudaGetSymbolAddress((void**)&xh,  g_xh);
    cudaGetSymbolAddress((void**)&w1h, g_w1h);
    cudaGetSymbolAddress((void**)&w2h, g_w2h);
    cudaGetSymbolAddress((void**)&hb,  g_hb);

    // fork side streams off the main (legacy default) stream
    cudaEventRecord(e_root, 0);
    cudaStreamWaitEvent(s1, e_root, 0);
    cudaStreamWaitEvent(s2, e_root, 0);

    // s1: prep (zero out, counters, convert x + W1) — needed before GEMM1
    prep_main_kernel<<<512, 256, 0, s1>>>(x, w1, out);
    cudaEventRecord(e_prep, s1);

    // s2: convert W2 — needed before GEMM2 only
    prep_w2_kernel<<<512, 256, 0, s2>>>(w2);
    cudaEventRecord(e_w2, s2);

    // main stream: routing chain (independent of prep)
    router_kernel<<<(NTOK * 32 + 255) / 256, 256>>>(x, wr);
    offsets_kernel<<<1, 64>>>(out, out_size);
    scatter_kernel<<<(SLOTS + 255) / 256, 256>>>();

    // join prep before GEMM1
    cudaStreamWaitEvent(0, e_prep, 0);
    moe_gemm<<<dim3(MAX_TILES, INTER / BN), 256, SMEM_TOTAL>>>(
        xh, w1h, HIDDEN, INTER, 0, hb, (float*)0);

    // join w2 before GEMM2
    cudaStreamWaitEvent(0, e_w2, 0);
    moe_gemm<<<dim3(MAX_TILES, HIDDEN / BN), 256, SMEM_TOTAL>>>(
        hb, w2h, INTER, HIDDEN, 1, (__half*)0, out);
}